// round 9
// baseline (speedup 1.0000x reference)
#include <cuda_runtime.h>
#include <cuda_bf16.h>
#include <cstdint>

#define BB 2048
#define SS 256
#define DD 768
#define CC 100
#define KSL 12         // K slices for gemm2 split-K (slice = 64)
#define NP 128         // padded N for gemm2
#define PSL 4          // pooling sequence slices (64 tokens each)
#define G1K 4          // gemm1 K slices (192 each)

// Scratch (no cudaMalloc allowed)
__device__ float g_h[(size_t)BB * DD];
__device__ float g_part[PSL][BB][DD];
__device__ float g_cntf[PSL][BB];
__device__ float g_p2[KSL][BB][NP];
__device__ float g_p1[G1K][BB][DD];
__device__ __nv_bfloat16 g_bow_hi[(size_t)BB * DD];
__device__ __nv_bfloat16 g_bow_lo[(size_t)BB * DD];
__device__ __nv_bfloat16 g_w1_hi[(size_t)DD * DD];
__device__ __nv_bfloat16 g_w1_lo[(size_t)DD * DD];

// ---------------------------------------------------------------------------
// Stage 1a: partial pooling. grid (BB, PSL); each block sums 64 tokens.
// ---------------------------------------------------------------------------
__global__ __launch_bounds__(192) void pool_partial(
    const int* __restrict__ ids,
    const int* __restrict__ mask,
    const float* __restrict__ emb)
{
    const int b  = blockIdx.x;
    const int sl = blockIdx.y;      // 0..3
    const int t  = threadIdx.x;     // 0..191

    __shared__ int s_ids[64];
    __shared__ int s_cnt;
    if (t == 0) s_cnt = 0;
    __syncthreads();

    if (t < 64) {
        const int off = b * SS + sl * 64 + t;
        if (mask[off] != 0) {
            const int pos = atomicAdd(&s_cnt, 1);
            s_ids[pos] = ids[off];
        }
    }
    __syncthreads();
    const int cnt = s_cnt;

    float4 acc = make_float4(0.f, 0.f, 0.f, 0.f);
    int s = 0;
    for (; s + 4 <= cnt; s += 4) {
        const float4 v0 = *((const float4*)(emb + (size_t)s_ids[s + 0] * DD) + t);
        const float4 v1 = *((const float4*)(emb + (size_t)s_ids[s + 1] * DD) + t);
        const float4 v2 = *((const float4*)(emb + (size_t)s_ids[s + 2] * DD) + t);
        const float4 v3 = *((const float4*)(emb + (size_t)s_ids[s + 3] * DD) + t);
        acc.x += (v0.x + v1.x) + (v2.x + v3.x);
        acc.y += (v0.y + v1.y) + (v2.y + v3.y);
        acc.z += (v0.z + v1.z) + (v2.z + v3.z);
        acc.w += (v0.w + v1.w) + (v2.w + v3.w);
    }
    for (; s < cnt; s++) {
        const float4 v = *((const float4*)(emb + (size_t)s_ids[s] * DD) + t);
        acc.x += v.x; acc.y += v.y; acc.z += v.z; acc.w += v.w;
    }
    *((float4*)(&g_part[sl][b][0]) + t) = acc;
    if (t == 0) g_cntf[sl][b] = (float)cnt;
}

// ---------------------------------------------------------------------------
// Stage 1b: combine slices, emit bow directly as bf16 (hi, lo) split.
// ---------------------------------------------------------------------------
__global__ __launch_bounds__(192) void pool_combine_split(void)
{
    const int b = blockIdx.x;
    const int t = threadIdx.x;
    const float inv = 1.0f / (g_cntf[0][b] + g_cntf[1][b] + g_cntf[2][b] + g_cntf[3][b]);
    float v[4] = {0.f, 0.f, 0.f, 0.f};
#pragma unroll
    for (int sl = 0; sl < PSL; sl++) {
        const float4 p = *((const float4*)(&g_part[sl][b][0]) + t);
        v[0] += p.x; v[1] += p.y; v[2] += p.z; v[3] += p.w;
    }
#pragma unroll
    for (int c = 0; c < 4; c++) v[c] *= inv;

    unsigned short hi[4], lo[4];
#pragma unroll
    for (int c = 0; c < 4; c++) {
        __nv_bfloat16 hb = __float2bfloat16(v[c]);
        float r = v[c] - __bfloat162float(hb);
        __nv_bfloat16 lb = __float2bfloat16(r);
        hi[c] = __bfloat16_as_ushort(hb);
        lo[c] = __bfloat16_as_ushort(lb);
    }
    const size_t idx = (size_t)b * DD + t * 4;
    uint2 ph = make_uint2(((uint32_t)hi[1] << 16) | hi[0], ((uint32_t)hi[3] << 16) | hi[2]);
    uint2 pl = make_uint2(((uint32_t)lo[1] << 16) | lo[0], ((uint32_t)lo[3] << 16) | lo[2]);
    *(uint2*)(g_bow_hi + idx) = ph;
    *(uint2*)(g_bow_lo + idx) = pl;
}

// ---------------------------------------------------------------------------
// Convert W1 fp32 -> (hi, lo) bf16 pair.
// ---------------------------------------------------------------------------
__global__ __launch_bounds__(256) void convert_w1(const float* __restrict__ W1)
{
    const int i = (blockIdx.x * 256 + threadIdx.x) * 4;
    const float4 v4 = *(const float4*)(W1 + i);
    const float v[4] = {v4.x, v4.y, v4.z, v4.w};
    unsigned short hi[4], lo[4];
#pragma unroll
    for (int c = 0; c < 4; c++) {
        __nv_bfloat16 hb = __float2bfloat16(v[c]);
        float r = v[c] - __bfloat162float(hb);
        __nv_bfloat16 lb = __float2bfloat16(r);
        hi[c] = __bfloat16_as_ushort(hb);
        lo[c] = __bfloat16_as_ushort(lb);
    }
    uint2 ph = make_uint2(((uint32_t)hi[1] << 16) | hi[0], ((uint32_t)hi[3] << 16) | hi[2]);
    uint2 pl = make_uint2(((uint32_t)lo[1] << 16) | lo[0], ((uint32_t)lo[3] << 16) | lo[2]);
    *(uint2*)(g_w1_hi + i) = ph;
    *(uint2*)(g_w1_lo + i) = pl;
}

// ---------------------------------------------------------------------------
// Tensor-core helpers
// ---------------------------------------------------------------------------
__device__ __forceinline__ uint32_t smem_u32(const void* p)
{
    return (uint32_t)__cvta_generic_to_shared(p);
}
__device__ __forceinline__ void ldsm4(uint32_t* r, uint32_t a)
{
    asm volatile("ldmatrix.sync.aligned.m8n8.x4.shared.b16 {%0,%1,%2,%3},[%4];"
                 : "=r"(r[0]), "=r"(r[1]), "=r"(r[2]), "=r"(r[3]) : "r"(a));
}
__device__ __forceinline__ void ldsm4t(uint32_t* r, uint32_t a)
{
    asm volatile("ldmatrix.sync.aligned.m8n8.x4.trans.shared.b16 {%0,%1,%2,%3},[%4];"
                 : "=r"(r[0]), "=r"(r[1]), "=r"(r[2]), "=r"(r[3]) : "r"(a));
}
__device__ __forceinline__ void mma_bf16(float* d, const uint32_t* a, const uint32_t* b)
{
    asm volatile(
        "mma.sync.aligned.m16n8k16.row.col.f32.bf16.bf16.f32 "
        "{%0,%1,%2,%3}, {%4,%5,%6,%7}, {%8,%9}, {%0,%1,%2,%3};"
        : "+f"(d[0]), "+f"(d[1]), "+f"(d[2]), "+f"(d[3])
        : "r"(a[0]), "r"(a[1]), "r"(a[2]), "r"(a[3]), "r"(b[0]), "r"(b[1]));
}

// ---------------------------------------------------------------------------
// gemm1 split-K via tensor cores, bf16-split x3: partial = bow_tile @ W1_tile.
// BM=128, BN=128, BK=16, K-slice=192. 8 warps (2x4); warp tile 64x32.
// grid (6, 16, 4) = 384 blocks. LDSM/MMA = 0.25.
// ---------------------------------------------------------------------------
#define AST 24    // A smem row stride (halves) = 48 B, conflict-free
#define BST 136   // B smem row stride (halves) = 272 B, conflict-free

__global__ __launch_bounds__(256) void gemm1_mma_sk(void)
{
    __shared__ __align__(16) __nv_bfloat16 sA[2][2][128 * AST];
    __shared__ __align__(16) __nv_bfloat16 sB[2][2][16 * BST];

    const int tid    = threadIdx.x;
    const int lane   = tid & 31;
    const int wid    = tid >> 5;
    const int warp_m = wid & 1;     // 0..1 -> 64 rows
    const int warp_n = wid >> 1;    // 0..3 -> 32 cols

    const int block_col = blockIdx.x * 128;
    const int block_row = blockIdx.y * 128;
    const int kbase     = blockIdx.z * (DD / G1K);   // 192

    // ---- fill mappings: 2 uint4 per thread for each of A and B ----
    // A tile: 128 rows x 16 k x 2 planes = 512 uint4
    int a_p[2], a_r[2], a_c[2];
    const __nv_bfloat16* Aptr[2];
#pragma unroll
    for (int e = 0; e < 2; e++) {
        const int idx = tid + e * 256;
        a_p[e] = idx >> 8;
        a_r[e] = (idx & 255) >> 1;
        a_c[e] = (idx & 1) * 8;
        Aptr[e] = (a_p[e] ? g_bow_lo : g_bow_hi)
                  + (size_t)(block_row + a_r[e]) * DD + kbase + a_c[e];
    }
    // B tile: 16 rows x 128 cols x 2 planes = 512 uint4
    int b_p[2], b_r[2], b_c[2];
    const __nv_bfloat16* Bptr[2];
#pragma unroll
    for (int e = 0; e < 2; e++) {
        const int idx = tid + e * 256;
        b_p[e] = idx >> 8;
        b_r[e] = (idx & 255) >> 4;
        b_c[e] = (idx & 15) * 8;
        Bptr[e] = (b_p[e] ? g_w1_lo : g_w1_hi)
                  + (size_t)(kbase + b_r[e]) * DD + block_col + b_c[e];
    }

    float acc[4][4][4];
#pragma unroll
    for (int mt = 0; mt < 4; mt++)
#pragma unroll
        for (int nt = 0; nt < 4; nt++)
#pragma unroll
            for (int q = 0; q < 4; q++) acc[mt][nt][q] = 0.f;

    // ---- preload k-tile 0 ----
#pragma unroll
    for (int e = 0; e < 2; e++) {
        *(uint4*)&sA[0][a_p[e]][a_r[e] * AST + a_c[e]] = *(const uint4*)(Aptr[e]);
        *(uint4*)&sB[0][b_p[e]][b_r[e] * BST + b_c[e]] = *(const uint4*)(Bptr[e]);
    }
    __syncthreads();

    const int NT = (DD / G1K) / 16;    // 12
    int aoff[4];
#pragma unroll
    for (int mt = 0; mt < 4; mt++)
        aoff[mt] = (warp_m * 64 + mt * 16 + (lane & 15)) * AST + (lane >> 4) * 8;
    int boff[2];
#pragma unroll
    for (int g = 0; g < 2; g++)
        boff[g] = (lane & 15) * BST + warp_n * 32 + g * 16 + (lane >> 4) * 8;

    for (int kt = 0; kt < NT; kt++) {
        const int cur = kt & 1;
        const int nxt = cur ^ 1;
        const bool has_next = (kt + 1 < NT);

        uint4 pa[2], pb[2];
        if (has_next) {
            const int k0 = (kt + 1) * 16;
#pragma unroll
            for (int e = 0; e < 2; e++) {
                pa[e] = *(const uint4*)(Aptr[e] + k0);
                pb[e] = *(const uint4*)(Bptr[e] + (size_t)k0 * DD);
            }
        }

        uint32_t af[2][4][4];     // [plane][mt]
#pragma unroll
        for (int p = 0; p < 2; p++)
#pragma unroll
            for (int mt = 0; mt < 4; mt++)
                ldsm4(af[p][mt], smem_u32(&sA[cur][p][aoff[mt]]));

        uint32_t bfr[2][4][2];    // [plane][nt]
#pragma unroll
        for (int p = 0; p < 2; p++)
#pragma unroll
            for (int g = 0; g < 2; g++) {
                uint32_t r[4];
                ldsm4t(r, smem_u32(&sB[cur][p][boff[g]]));
                bfr[p][2 * g + 0][0] = r[0]; bfr[p][2 * g + 0][1] = r[1];
                bfr[p][2 * g + 1][0] = r[2]; bfr[p][2 * g + 1][1] = r[3];
            }

#pragma unroll
        for (int mt = 0; mt < 4; mt++)
#pragma unroll
            for (int nt = 0; nt < 4; nt++) {
                mma_bf16(acc[mt][nt], af[0][mt], bfr[0][nt]);  // hi*hi
                mma_bf16(acc[mt][nt], af[0][mt], bfr[1][nt]);  // hi*lo
                mma_bf16(acc[mt][nt], af[1][mt], bfr[0][nt]);  // lo*hi
            }

        if (has_next) {
#pragma unroll
            for (int e = 0; e < 2; e++) {
                *(uint4*)&sA[nxt][a_p[e]][a_r[e] * AST + a_c[e]] = pa[e];
                *(uint4*)&sB[nxt][b_p[e]][b_r[e] * BST + b_c[e]] = pb[e];
            }
            __syncthreads();
        }
    }

    // ---- store fp32 partials ----
    float* P = &g_p1[blockIdx.z][0][0];
#pragma unroll
    for (int mt = 0; mt < 4; mt++) {
        const int row0 = block_row + warp_m * 64 + mt * 16 + (lane >> 2);
#pragma unroll
        for (int nt = 0; nt < 4; nt++) {
            const int col = block_col + warp_n * 32 + nt * 8 + (lane & 3) * 2;
            *(float2*)(P + (size_t)row0 * DD + col) =
                make_float2(acc[mt][nt][0], acc[mt][nt][1]);
            *(float2*)(P + (size_t)(row0 + 8) * DD + col) =
                make_float2(acc[mt][nt][2], acc[mt][nt][3]);
        }
    }
}

// ---------------------------------------------------------------------------
// reduce1: h = relu(sum_z g_p1[z] + b1). float4 per thread, grid 1536.
// ---------------------------------------------------------------------------
__global__ __launch_bounds__(256) void reduce1(
    const float* __restrict__ bias,
    float* __restrict__ h)
{
    const int i = (blockIdx.x * 256 + threadIdx.x) * 4;
    const int col = i - (i / DD) * DD;   // DD % 4 == 0 -> all 4 in same row
    float4 s = *(const float4*)(&g_p1[0][0][0] + i);
#pragma unroll
    for (int z = 1; z < G1K; z++) {
        const float4 p = *(const float4*)(&g_p1[z][0][0] + i);
        s.x += p.x; s.y += p.y; s.z += p.z; s.w += p.w;
    }
    const float4 bv = *(const float4*)(bias + col);
    s.x = fmaxf(s.x + bv.x, 0.f);
    s.y = fmaxf(s.y + bv.y, 0.f);
    s.z = fmaxf(s.z + bv.z, 0.f);
    s.w = fmaxf(s.w + bv.w, 0.f);
    *(float4*)(h + i) = s;
}

// ---------------------------------------------------------------------------
// gemm2 split-K (fp32 SIMT): partial[ksl] = h[64 rows, kslice=64] @ W2
// ---------------------------------------------------------------------------
__global__ __launch_bounds__(256) void gemm_splitk(
    const float* __restrict__ A,
    const float* __restrict__ Bm)
{
    const int BK = 16;
    __shared__ float As[BK][64 + 4];
    __shared__ float Bs[BK][NP];

    const int tid = threadIdx.x;
    const int tx  = tid & 15;
    const int ty  = tid >> 4;

    const int ksl       = blockIdx.x;
    const int block_row = blockIdx.y * 64;
    const int kbase     = ksl * (DD / KSL);

    const int a_row = tid >> 2;
    const int a_c4  = (tid & 3) * 4;
    const int b_idx0 = tid, b_idx1 = tid + 256;
    const int b_r0 = b_idx0 >> 5, b_c0 = (b_idx0 & 31) * 4;
    const int b_r1 = b_idx1 >> 5, b_c1 = (b_idx1 & 31) * 4;

    float acc[4][8];
#pragma unroll
    for (int i = 0; i < 4; i++)
#pragma unroll
        for (int j = 0; j < 8; j++) acc[i][j] = 0.f;

    for (int k0 = 0; k0 < DD / KSL; k0 += BK) {
        {
            const float4 av = *(const float4*)(A + (size_t)(block_row + a_row) * DD + kbase + k0 + a_c4);
            As[a_c4 + 0][a_row] = av.x;
            As[a_c4 + 1][a_row] = av.y;
            As[a_c4 + 2][a_row] = av.z;
            As[a_c4 + 3][a_row] = av.w;
        }
        {
            const float* src0 = Bm + (size_t)(kbase + k0 + b_r0) * CC;
            const float* src1 = Bm + (size_t)(kbase + k0 + b_r1) * CC;
            if (b_c0 + 3 < CC) {
                *(float4*)&Bs[b_r0][b_c0] = *(const float4*)(src0 + b_c0);
            } else {
                Bs[b_r0][b_c0 + 0] = (b_c0 + 0 < CC) ? src0[b_c0 + 0] : 0.f;
                Bs[b_r0][b_c0 + 1] = (b_c0 + 1 < CC) ? src0[b_c0 + 1] : 0.f;
                Bs[b_r0][b_c0 + 2] = (b_c0 + 2 < CC) ? src0[b_c0 + 2] : 0.f;
                Bs[b_r0][b_c0 + 3] = (b_c0 + 3 < CC) ? src0[b_c0 + 3] : 0.f;
            }
            if (b_c1 + 3 < CC) {
                *(float4*)&Bs[b_r1][b_c1] = *(const float4*)(src1 + b_c1);
            } else {
                Bs[b_r1][b_c1 + 0] = (b_c1 + 0 < CC) ? src1[b_c1 + 0] : 0.f;
                Bs[b_r1][b_c1 + 1] = (b_c1 + 1 < CC) ? src1[b_c1 + 1] : 0.f;
                Bs[b_r1][b_c1 + 2] = (b_c1 + 2 < CC) ? src1[b_c1 + 2] : 0.f;
                Bs[b_r1][b_c1 + 3] = (b_c1 + 3 < CC) ? src1[b_c1 + 3] : 0.f;
            }
        }
        __syncthreads();

#pragma unroll
        for (int k = 0; k < BK; k++) {
            float a[4], bb[8];
#pragma unroll
            for (int i = 0; i < 4; i++) a[i] = As[k][ty * 4 + i];
            const float4 bv0 = *(const float4*)&Bs[k][tx * 8 + 0];
            const float4 bv1 = *(const float4*)&Bs[k][tx * 8 + 4];
            bb[0] = bv0.x; bb[1] = bv0.y; bb[2] = bv0.z; bb[3] = bv0.w;
            bb[4] = bv1.x; bb[5] = bv1.y; bb[6] = bv1.z; bb[7] = bv1.w;
#pragma unroll
            for (int i = 0; i < 4; i++)
#pragma unroll
                for (int j = 0; j < 8; j++)
                    acc[i][j] = fmaf(a[i], bb[j], acc[i][j]);
        }
        __syncthreads();
    }

#pragma unroll
    for (int i = 0; i < 4; i++) {
        const int row = block_row + ty * 4 + i;
        float4 v0 = make_float4(acc[i][0], acc[i][1], acc[i][2], acc[i][3]);
        float4 v1 = make_float4(acc[i][4], acc[i][5], acc[i][6], acc[i][7]);
        *(float4*)(&g_p2[ksl][row][tx * 8 + 0]) = v0;
        *(float4*)(&g_p2[ksl][row][tx * 8 + 4]) = v1;
    }
}

// ---------------------------------------------------------------------------
// Reduce split-K partials + bias, write both output copies.
// ---------------------------------------------------------------------------
__global__ __launch_bounds__(256) void reduce_kernel(
    const float* __restrict__ bias,
    float* __restrict__ out,
    float* __restrict__ out2)
{
    const int idx = blockIdx.x * 256 + threadIdx.x;
    if (idx >= BB * CC) return;
    const int b = idx / CC;
    const int c = idx - b * CC;
    float v = bias[c];
#pragma unroll
    for (int s = 0; s < KSL; s++) v += g_p2[s][b][c];
    out[idx] = v;
    if (out2) out2[idx] = v;
}

// ---------------------------------------------------------------------------
extern "C" void kernel_launch(void* const* d_in, const int* in_sizes, int n_in,
                              void* d_out, int out_size)
{
    const int*   input_ids = (const int*)d_in[0];
    const int*   attn_mask = (const int*)d_in[1];
    const float* emb       = (const float*)d_in[2];
    const float* W1        = (const float*)d_in[3];
    const float* b1        = (const float*)d_in[4];
    const float* W2        = (const float*)d_in[5];
    const float* b2        = (const float*)d_in[6];
    float*       out       = (float*)d_out;

    float* h; cudaGetSymbolAddress((void**)&h, g_h);

    // W1 -> bf16 hi/lo
    convert_w1<<<(DD * DD) / (256 * 4), 256>>>(W1);

    // Stage 1: pooling (4 sequence slices, then combine + bf16 split)
    {
        dim3 grid(BB, PSL);
        pool_partial<<<grid, 192>>>(input_ids, attn_mask, emb);
        pool_combine_split<<<BB, 192>>>();
    }

    // Stage 2: h = relu(bow @ W1 + b1), tensor cores, split-K x4
    {
        dim3 grid(DD / 128, BB / 128, G1K);   // (6, 16, 4) = 384 blocks
        gemm1_mma_sk<<<grid, 256>>>();
        reduce1<<<(BB * DD) / (256 * 4), 256>>>(b1, h);
    }

    // Stage 3: scores = h @ W2 + b2 (split-K + reduce), duplicated output
    {
        dim3 grid(KSL, BB / 64);              // (12, 32) = 384 blocks
        gemm_splitk<<<grid, 256>>>(h, W2);
        float* out2 = (out_size >= 2 * BB * CC) ? (out + (size_t)BB * CC) : nullptr;
        reduce_kernel<<<(BB * CC + 255) / 256, 256>>>(b2, out, out2);
    }
}

// round 11
// speedup vs baseline: 1.0333x; 1.0333x over previous
#include <cuda_runtime.h>
#include <cuda_bf16.h>
#include <cstdint>

#define BB 2048
#define SS 256
#define DD 768
#define CC 100
#define KSL 12         // K slices for gemm2 split-K (slice = 64)
#define NP 128         // padded N for gemm2
#define PSL 4          // pooling sequence slices (64 tokens each)

// Scratch (no cudaMalloc allowed)
__device__ float g_h[(size_t)BB * DD];
__device__ float g_part[PSL][BB][DD];
__device__ float g_cntf[PSL][BB];
__device__ float g_p2[KSL][BB][NP];
__device__ __nv_bfloat16 g_bow_hi[(size_t)BB * DD];
__device__ __nv_bfloat16 g_bow_lo[(size_t)BB * DD];
__device__ __nv_bfloat16 g_w1_hi[(size_t)DD * DD];   // W1 row-major [K][N]
__device__ __nv_bfloat16 g_w1_lo[(size_t)DD * DD];

// ---------------------------------------------------------------------------
// Stage 1a: partial pooling. grid (BB, PSL); each block sums 64 tokens.
// ---------------------------------------------------------------------------
__global__ __launch_bounds__(192) void pool_partial(
    const int* __restrict__ ids,
    const int* __restrict__ mask,
    const float* __restrict__ emb)
{
    const int b  = blockIdx.x;
    const int sl = blockIdx.y;
    const int t  = threadIdx.x;

    __shared__ int s_ids[64];
    __shared__ int s_cnt;
    if (t == 0) s_cnt = 0;
    __syncthreads();

    if (t < 64) {
        const int off = b * SS + sl * 64 + t;
        if (mask[off] != 0) {
            const int pos = atomicAdd(&s_cnt, 1);
            s_ids[pos] = ids[off];
        }
    }
    __syncthreads();
    const int cnt = s_cnt;

    float4 acc = make_float4(0.f, 0.f, 0.f, 0.f);
    int s = 0;
    for (; s + 4 <= cnt; s += 4) {
        const float4 v0 = *((const float4*)(emb + (size_t)s_ids[s + 0] * DD) + t);
        const float4 v1 = *((const float4*)(emb + (size_t)s_ids[s + 1] * DD) + t);
        const float4 v2 = *((const float4*)(emb + (size_t)s_ids[s + 2] * DD) + t);
        const float4 v3 = *((const float4*)(emb + (size_t)s_ids[s + 3] * DD) + t);
        acc.x += (v0.x + v1.x) + (v2.x + v3.x);
        acc.y += (v0.y + v1.y) + (v2.y + v3.y);
        acc.z += (v0.z + v1.z) + (v2.z + v3.z);
        acc.w += (v0.w + v1.w) + (v2.w + v3.w);
    }
    for (; s < cnt; s++) {
        const float4 v = *((const float4*)(emb + (size_t)s_ids[s] * DD) + t);
        acc.x += v.x; acc.y += v.y; acc.z += v.z; acc.w += v.w;
    }
    *((float4*)(&g_part[sl][b][0]) + t) = acc;
    if (t == 0) g_cntf[sl][b] = (float)cnt;
}

// ---------------------------------------------------------------------------
// Stage 1b: combine slices, emit bow as bf16 (hi, lo) split.
// ---------------------------------------------------------------------------
__global__ __launch_bounds__(192) void pool_combine_split(void)
{
    const int b = blockIdx.x;
    const int t = threadIdx.x;
    const float inv = 1.0f / (g_cntf[0][b] + g_cntf[1][b] + g_cntf[2][b] + g_cntf[3][b]);
    float v[4] = {0.f, 0.f, 0.f, 0.f};
#pragma unroll
    for (int sl = 0; sl < PSL; sl++) {
        const float4 p = *((const float4*)(&g_part[sl][b][0]) + t);
        v[0] += p.x; v[1] += p.y; v[2] += p.z; v[3] += p.w;
    }
#pragma unroll
    for (int c = 0; c < 4; c++) v[c] *= inv;

    unsigned short hi[4], lo[4];
#pragma unroll
    for (int c = 0; c < 4; c++) {
        __nv_bfloat16 hb = __float2bfloat16(v[c]);
        float r = v[c] - __bfloat162float(hb);
        __nv_bfloat16 lb = __float2bfloat16(r);
        hi[c] = __bfloat16_as_ushort(hb);
        lo[c] = __bfloat16_as_ushort(lb);
    }
    const size_t idx = (size_t)b * DD + t * 4;
    uint2 ph = make_uint2(((uint32_t)hi[1] << 16) | hi[0], ((uint32_t)hi[3] << 16) | hi[2]);
    uint2 pl = make_uint2(((uint32_t)lo[1] << 16) | lo[0], ((uint32_t)lo[3] << 16) | lo[2]);
    *(uint2*)(g_bow_hi + idx) = ph;
    *(uint2*)(g_bow_lo + idx) = pl;
}

// ---------------------------------------------------------------------------
// Convert W1 fp32 -> (hi, lo) bf16 pair (row-major [K][N]).
// ---------------------------------------------------------------------------
__global__ __launch_bounds__(256) void convert_w1(const float* __restrict__ W1)
{
    const int i = (blockIdx.x * 256 + threadIdx.x) * 4;
    const float4 v4 = *(const float4*)(W1 + i);
    const float v[4] = {v4.x, v4.y, v4.z, v4.w};
    unsigned short hi[4], lo[4];
#pragma unroll
    for (int c = 0; c < 4; c++) {
        __nv_bfloat16 hb = __float2bfloat16(v[c]);
        float r = v[c] - __bfloat162float(hb);
        __nv_bfloat16 lb = __float2bfloat16(r);
        hi[c] = __bfloat16_as_ushort(hb);
        lo[c] = __bfloat16_as_ushort(lb);
    }
    uint2 ph = make_uint2(((uint32_t)hi[1] << 16) | hi[0], ((uint32_t)hi[3] << 16) | hi[2]);
    uint2 pl = make_uint2(((uint32_t)lo[1] << 16) | lo[0], ((uint32_t)lo[3] << 16) | lo[2]);
    *(uint2*)(g_w1_hi + i) = ph;
    *(uint2*)(g_w1_lo + i) = pl;
}

// ---------------------------------------------------------------------------
// Tensor-core helpers (mma.sync path; tcgen05 unavailable on this toolchain)
// ---------------------------------------------------------------------------
__device__ __forceinline__ uint32_t smem_u32(const void* p)
{
    return (uint32_t)__cvta_generic_to_shared(p);
}
__device__ __forceinline__ void ldsm4(uint32_t* r, uint32_t a)
{
    asm volatile("ldmatrix.sync.aligned.m8n8.x4.shared.b16 {%0,%1,%2,%3},[%4];"
                 : "=r"(r[0]), "=r"(r[1]), "=r"(r[2]), "=r"(r[3]) : "r"(a));
}
__device__ __forceinline__ void ldsm4t(uint32_t* r, uint32_t a)
{
    asm volatile("ldmatrix.sync.aligned.m8n8.x4.trans.shared.b16 {%0,%1,%2,%3},[%4];"
                 : "=r"(r[0]), "=r"(r[1]), "=r"(r[2]), "=r"(r[3]) : "r"(a));
}
__device__ __forceinline__ void mma_bf16(float* d, const uint32_t* a, const uint32_t* b)
{
    asm volatile(
        "mma.sync.aligned.m16n8k16.row.col.f32.bf16.bf16.f32 "
        "{%0,%1,%2,%3}, {%4,%5,%6,%7}, {%8,%9}, {%0,%1,%2,%3};"
        : "+f"(d[0]), "+f"(d[1]), "+f"(d[2]), "+f"(d[3])
        : "r"(a[0]), "r"(a[1]), "r"(a[2]), "r"(a[3]), "r"(b[0]), "r"(b[1]));
}

// ---------------------------------------------------------------------------
// gemm1: h = relu(bow @ W1 + b1), bf16-split x3 (hi*hi + hi*lo + lo*hi).
// BM=128, BN=96, BK=16. grid (8, 16) = 128 CTAs -> exactly ONE wave, 1/SM.
// 8 warps as 4(m) x 2(n); warp tile 32 rows x 48 cols; mt=2, nt=6.
// LDSM per k-iter: A 2x2=4 ldsm4, B 2x3=6 ldsm4t -> 10 vs 36 MMA (ratio .28).
// ---------------------------------------------------------------------------
#define AST 24     // A smem row stride (halves) = 48 B, conflict-free
#define BST 104    // B smem row stride (halves) = 208 B, 16B mult, conflict-free

__global__ __launch_bounds__(256) void gemm1_mma96(
    const float* __restrict__ bias,
    float* __restrict__ h)
{
    __shared__ __align__(16) __nv_bfloat16 sA[2][2][128 * AST];
    __shared__ __align__(16) __nv_bfloat16 sB[2][2][16 * BST];

    const int tid    = threadIdx.x;
    const int lane   = tid & 31;
    const int wid    = tid >> 5;
    const int warp_m = wid & 3;     // 0..3 -> 32 rows each
    const int warp_n = wid >> 2;    // 0..1 -> 48 cols each

    const int block_row = blockIdx.y * 128;
    const int block_col = blockIdx.x * 96;

    // ---- A fill: 512 uint4 units (128r x 16k x 2 planes); 2 per thread ----
    int a_p[2], a_r[2], a_c[2];
    const __nv_bfloat16* Aptr[2];
#pragma unroll
    for (int e = 0; e < 2; e++) {
        const int u = tid + e * 256;
        a_p[e] = u >> 8;
        a_r[e] = (u & 255) >> 1;
        a_c[e] = (u & 1) * 8;
        Aptr[e] = (a_p[e] ? g_bow_lo : g_bow_hi)
                  + (size_t)(block_row + a_r[e]) * DD + a_c[e];
    }
    // ---- B fill: 384 uint4 units (16k x 12 colgrps x 2 planes) ----
    // unit u: p = u/192, r = (u%192)/12, cg = u%12. Threads 0..255 do u=tid;
    // threads 0..127 also do u=tid+256.
    int b_p[2], b_r[2], b_c[2], b_ok[2];
    const __nv_bfloat16* Bptr[2];
#pragma unroll
    for (int e = 0; e < 2; e++) {
        const int u = tid + e * 256;
        b_ok[e] = (u < 384);
        const int uu = b_ok[e] ? u : 0;
        b_p[e] = uu / 192;
        const int rem = uu - b_p[e] * 192;
        b_r[e] = rem / 12;
        b_c[e] = (rem - b_r[e] * 12) * 8;
        Bptr[e] = (b_p[e] ? g_w1_lo : g_w1_hi)
                  + (size_t)b_r[e] * DD + block_col + b_c[e];
    }

    float acc[2][6][4];
#pragma unroll
    for (int mt = 0; mt < 2; mt++)
#pragma unroll
        for (int nt = 0; nt < 6; nt++)
#pragma unroll
            for (int q = 0; q < 4; q++) acc[mt][nt][q] = 0.f;

    // ---- preload k-tile 0 into stage 0 ----
#pragma unroll
    for (int e = 0; e < 2; e++) {
        *(uint4*)&sA[0][a_p[e]][a_r[e] * AST + a_c[e]] = *(const uint4*)(Aptr[e]);
        if (b_ok[e])
            *(uint4*)&sB[0][b_p[e]][b_r[e] * BST + b_c[e]] = *(const uint4*)(Bptr[e]);
    }
    __syncthreads();

    const int NT = DD / 16;   // 48
    int aoff[2];
#pragma unroll
    for (int mt = 0; mt < 2; mt++)
        aoff[mt] = (warp_m * 32 + mt * 16 + (lane & 15)) * AST + (lane >> 4) * 8;
    int boff[3];
#pragma unroll
    for (int g = 0; g < 3; g++)
        boff[g] = (lane & 15) * BST + warp_n * 48 + g * 16 + (lane >> 4) * 8;

    for (int kt = 0; kt < NT; kt++) {
        const int cur = kt & 1;
        const int nxt = cur ^ 1;
        const bool has_next = (kt + 1 < NT);

        uint4 pa[2], pb[2];
        if (has_next) {
            const int k0 = (kt + 1) * 16;
#pragma unroll
            for (int e = 0; e < 2; e++) {
                pa[e] = *(const uint4*)(Aptr[e] + k0);
                if (b_ok[e]) pb[e] = *(const uint4*)(Bptr[e] + (size_t)k0 * DD);
            }
        }

        uint32_t af[2][2][4];     // [plane][mt]
#pragma unroll
        for (int p = 0; p < 2; p++)
#pragma unroll
            for (int mt = 0; mt < 2; mt++)
                ldsm4(af[p][mt], smem_u32(&sA[cur][p][aoff[mt]]));

        uint32_t bfr[2][6][2];    // [plane][nt]
#pragma unroll
        for (int p = 0; p < 2; p++)
#pragma unroll
            for (int g = 0; g < 3; g++) {
                uint32_t r[4];
                ldsm4t(r, smem_u32(&sB[cur][p][boff[g]]));
                bfr[p][2 * g + 0][0] = r[0]; bfr[p][2 * g + 0][1] = r[1];
                bfr[p][2 * g + 1][0] = r[2]; bfr[p][2 * g + 1][1] = r[3];
            }

#pragma unroll
        for (int mt = 0; mt < 2; mt++)
#pragma unroll
            for (int nt = 0; nt < 6; nt++) {
                mma_bf16(acc[mt][nt], af[0][mt], bfr[0][nt]);  // hi*hi
                mma_bf16(acc[mt][nt], af[0][mt], bfr[1][nt]);  // hi*lo
                mma_bf16(acc[mt][nt], af[1][mt], bfr[0][nt]);  // lo*hi
            }

        if (has_next) {
#pragma unroll
            for (int e = 0; e < 2; e++) {
                *(uint4*)&sA[nxt][a_p[e]][a_r[e] * AST + a_c[e]] = pa[e];
                if (b_ok[e])
                    *(uint4*)&sB[nxt][b_p[e]][b_r[e] * BST + b_c[e]] = pb[e];
            }
            __syncthreads();
        }
    }

    // ---- epilogue: bias + relu ----
#pragma unroll
    for (int mt = 0; mt < 2; mt++) {
        const int row0 = block_row + warp_m * 32 + mt * 16 + (lane >> 2);
#pragma unroll
        for (int nt = 0; nt < 6; nt++) {
            const int col = block_col + warp_n * 48 + nt * 8 + (lane & 3) * 2;
            const float b0 = bias[col], b1v = bias[col + 1];
            float2 v0, v1;
            v0.x = fmaxf(acc[mt][nt][0] + b0, 0.f);
            v0.y = fmaxf(acc[mt][nt][1] + b1v, 0.f);
            v1.x = fmaxf(acc[mt][nt][2] + b0, 0.f);
            v1.y = fmaxf(acc[mt][nt][3] + b1v, 0.f);
            *(float2*)(h + (size_t)row0 * DD + col)       = v0;
            *(float2*)(h + (size_t)(row0 + 8) * DD + col) = v1;
        }
    }
}

// ---------------------------------------------------------------------------
// gemm2 split-K (fp32 SIMT): partial[ksl] = h[64 rows, kslice=64] @ W2
// ---------------------------------------------------------------------------
__global__ __launch_bounds__(256) void gemm_splitk(
    const float* __restrict__ A,
    const float* __restrict__ Bm)
{
    const int BK = 16;
    __shared__ float As[BK][64 + 4];
    __shared__ float Bs[BK][NP];

    const int tid = threadIdx.x;
    const int tx  = tid & 15;
    const int ty  = tid >> 4;

    const int ksl       = blockIdx.x;
    const int block_row = blockIdx.y * 64;
    const int kbase     = ksl * (DD / KSL);

    const int a_row = tid >> 2;
    const int a_c4  = (tid & 3) * 4;
    const int b_idx0 = tid, b_idx1 = tid + 256;
    const int b_r0 = b_idx0 >> 5, b_c0 = (b_idx0 & 31) * 4;
    const int b_r1 = b_idx1 >> 5, b_c1 = (b_idx1 & 31) * 4;

    float acc[4][8];
#pragma unroll
    for (int i = 0; i < 4; i++)
#pragma unroll
        for (int j = 0; j < 8; j++) acc[i][j] = 0.f;

    for (int k0 = 0; k0 < DD / KSL; k0 += BK) {
        {
            const float4 av = *(const float4*)(A + (size_t)(block_row + a_row) * DD + kbase + k0 + a_c4);
            As[a_c4 + 0][a_row] = av.x;
            As[a_c4 + 1][a_row] = av.y;
            As[a_c4 + 2][a_row] = av.z;
            As[a_c4 + 3][a_row] = av.w;
        }
        {
            const float* src0 = Bm + (size_t)(kbase + k0 + b_r0) * CC;
            const float* src1 = Bm + (size_t)(kbase + k0 + b_r1) * CC;
            if (b_c0 + 3 < CC) {
                *(float4*)&Bs[b_r0][b_c0] = *(const float4*)(src0 + b_c0);
            } else {
                Bs[b_r0][b_c0 + 0] = (b_c0 + 0 < CC) ? src0[b_c0 + 0] : 0.f;
                Bs[b_r0][b_c0 + 1] = (b_c0 + 1 < CC) ? src0[b_c0 + 1] : 0.f;
                Bs[b_r0][b_c0 + 2] = (b_c0 + 2 < CC) ? src0[b_c0 + 2] : 0.f;
                Bs[b_r0][b_c0 + 3] = (b_c0 + 3 < CC) ? src0[b_c0 + 3] : 0.f;
            }
            if (b_c1 + 3 < CC) {
                *(float4*)&Bs[b_r1][b_c1] = *(const float4*)(src1 + b_c1);
            } else {
                Bs[b_r1][b_c1 + 0] = (b_c1 + 0 < CC) ? src1[b_c1 + 0] : 0.f;
                Bs[b_r1][b_c1 + 1] = (b_c1 + 1 < CC) ? src1[b_c1 + 1] : 0.f;
                Bs[b_r1][b_c1 + 2] = (b_c1 + 2 < CC) ? src1[b_c1 + 2] : 0.f;
                Bs[b_r1][b_c1 + 3] = (b_c1 + 3 < CC) ? src1[b_c1 + 3] : 0.f;
            }
        }
        __syncthreads();

#pragma unroll
        for (int k = 0; k < BK; k++) {
            float a[4], bb[8];
#pragma unroll
            for (int i = 0; i < 4; i++) a[i] = As[k][ty * 4 + i];
            const float4 bv0 = *(const float4*)&Bs[k][tx * 8 + 0];
            const float4 bv1 = *(const float4*)&Bs[k][tx * 8 + 4];
            bb[0] = bv0.x; bb[1] = bv0.y; bb[2] = bv0.z; bb[3] = bv0.w;
            bb[4] = bv1.x; bb[5] = bv1.y; bb[6] = bv1.z; bb[7] = bv1.w;
#pragma unroll
            for (int i = 0; i < 4; i++)
#pragma unroll
                for (int j = 0; j < 8; j++)
                    acc[i][j] = fmaf(a[i], bb[j], acc[i][j]);
        }
        __syncthreads();
    }

#pragma unroll
    for (int i = 0; i < 4; i++) {
        const int row = block_row + ty * 4 + i;
        float4 v0 = make_float4(acc[i][0], acc[i][1], acc[i][2], acc[i][3]);
        float4 v1 = make_float4(acc[i][4], acc[i][5], acc[i][6], acc[i][7]);
        *(float4*)(&g_p2[ksl][row][tx * 8 + 0]) = v0;
        *(float4*)(&g_p2[ksl][row][tx * 8 + 4]) = v1;
    }
}

// ---------------------------------------------------------------------------
// Reduce split-K partials + bias, write both output copies.
// ---------------------------------------------------------------------------
__global__ __launch_bounds__(256) void reduce_kernel(
    const float* __restrict__ bias,
    float* __restrict__ out,
    float* __restrict__ out2)
{
    const int idx = blockIdx.x * 256 + threadIdx.x;
    if (idx >= BB * CC) return;
    const int b = idx / CC;
    const int c = idx - b * CC;
    float v = bias[c];
#pragma unroll
    for (int s = 0; s < KSL; s++) v += g_p2[s][b][c];
    out[idx] = v;
    if (out2) out2[idx] = v;
}

// ---------------------------------------------------------------------------
extern "C" void kernel_launch(void* const* d_in, const int* in_sizes, int n_in,
                              void* d_out, int out_size)
{
    const int*   input_ids = (const int*)d_in[0];
    const int*   attn_mask = (const int*)d_in[1];
    const float* emb       = (const float*)d_in[2];
    const float* W1        = (const float*)d_in[3];
    const float* b1        = (const float*)d_in[4];
    const float* W2        = (const float*)d_in[5];
    const float* b2        = (const float*)d_in[6];
    float*       out       = (float*)d_out;

    float* h; cudaGetSymbolAddress((void**)&h, g_h);

    // W1 -> bf16 hi/lo
    convert_w1<<<(DD * DD) / (256 * 4), 256>>>(W1);

    // Stage 1: pooling (4 sequence slices, then combine + bf16 split)
    {
        dim3 grid(BB, PSL);
        pool_partial<<<grid, 192>>>(input_ids, attn_mask, emb);
        pool_combine_split<<<BB, 192>>>();
    }

    // Stage 2: h = relu(bow @ W1 + b1), mma.sync bf16-split, single wave
    {
        dim3 grid(DD / 96, BB / 128);    // (8, 16) = 128 CTAs
        gemm1_mma96<<<grid, 256>>>(b1, h);
    }

    // Stage 3: scores = h @ W2 + b2 (split-K + reduce), duplicated output
    {
        dim3 grid(KSL, BB / 64);         // (12, 32)
        gemm_splitk<<<grid, 256>>>(h, W2);
        float* out2 = (out_size >= 2 * BB * CC) ? (out + (size_t)BB * CC) : nullptr;
        reduce_kernel<<<(BB * CC + 255) / 256, 256>>>(b2, out, out2);
    }
}

// round 12
// speedup vs baseline: 1.1065x; 1.0708x over previous
#include <cuda_runtime.h>
#include <cuda_bf16.h>
#include <cstdint>

#define BB 2048
#define SS 256
#define DD 768
#define CC 100
#define NP 128         // padded N for gemm2
#define PSL 4          // pooling sequence slices (64 tokens each)
#define G2K 4          // gemm2 K slices (192 each)

// Scratch (no cudaMalloc allowed)
__device__ float g_part[PSL][BB][DD];
__device__ float g_cntf[PSL][BB];
__device__ float g_p2[G2K][BB][NP];
__device__ __nv_bfloat16 g_bow_hi[(size_t)BB * DD];
__device__ __nv_bfloat16 g_bow_lo[(size_t)BB * DD];
__device__ __nv_bfloat16 g_w1_hi[(size_t)DD * DD];    // W1 row-major [K][N]
__device__ __nv_bfloat16 g_w1_lo[(size_t)DD * DD];
__device__ __nv_bfloat16 g_w2p_hi[(size_t)DD * NP];   // W2 padded [K][128]
__device__ __nv_bfloat16 g_w2p_lo[(size_t)DD * NP];
__device__ __nv_bfloat16 g_h_hi[(size_t)BB * DD];
__device__ __nv_bfloat16 g_h_lo[(size_t)BB * DD];

// ---------------------------------------------------------------------------
// Stage 1a: partial pooling. grid (BB, PSL); each block sums 64 tokens.
// ---------------------------------------------------------------------------
__global__ __launch_bounds__(192) void pool_partial(
    const int* __restrict__ ids,
    const int* __restrict__ mask,
    const float* __restrict__ emb)
{
    const int b  = blockIdx.x;
    const int sl = blockIdx.y;
    const int t  = threadIdx.x;

    __shared__ int s_ids[64];
    __shared__ int s_cnt;
    if (t == 0) s_cnt = 0;
    __syncthreads();

    if (t < 64) {
        const int off = b * SS + sl * 64 + t;
        if (mask[off] != 0) {
            const int pos = atomicAdd(&s_cnt, 1);
            s_ids[pos] = ids[off];
        }
    }
    __syncthreads();
    const int cnt = s_cnt;

    float4 acc = make_float4(0.f, 0.f, 0.f, 0.f);
    int s = 0;
    for (; s + 4 <= cnt; s += 4) {
        const float4 v0 = *((const float4*)(emb + (size_t)s_ids[s + 0] * DD) + t);
        const float4 v1 = *((const float4*)(emb + (size_t)s_ids[s + 1] * DD) + t);
        const float4 v2 = *((const float4*)(emb + (size_t)s_ids[s + 2] * DD) + t);
        const float4 v3 = *((const float4*)(emb + (size_t)s_ids[s + 3] * DD) + t);
        acc.x += (v0.x + v1.x) + (v2.x + v3.x);
        acc.y += (v0.y + v1.y) + (v2.y + v3.y);
        acc.z += (v0.z + v1.z) + (v2.z + v3.z);
        acc.w += (v0.w + v1.w) + (v2.w + v3.w);
    }
    for (; s < cnt; s++) {
        const float4 v = *((const float4*)(emb + (size_t)s_ids[s] * DD) + t);
        acc.x += v.x; acc.y += v.y; acc.z += v.z; acc.w += v.w;
    }
    *((float4*)(&g_part[sl][b][0]) + t) = acc;
    if (t == 0) g_cntf[sl][b] = (float)cnt;
}

// ---------------------------------------------------------------------------
// Stage 1b: combine slices, emit bow as bf16 (hi, lo) split.
// ---------------------------------------------------------------------------
__global__ __launch_bounds__(192) void pool_combine_split(void)
{
    const int b = blockIdx.x;
    const int t = threadIdx.x;
    const float inv = 1.0f / (g_cntf[0][b] + g_cntf[1][b] + g_cntf[2][b] + g_cntf[3][b]);
    float v[4] = {0.f, 0.f, 0.f, 0.f};
#pragma unroll
    for (int sl = 0; sl < PSL; sl++) {
        const float4 p = *((const float4*)(&g_part[sl][b][0]) + t);
        v[0] += p.x; v[1] += p.y; v[2] += p.z; v[3] += p.w;
    }
#pragma unroll
    for (int c = 0; c < 4; c++) v[c] *= inv;

    unsigned short hi[4], lo[4];
#pragma unroll
    for (int c = 0; c < 4; c++) {
        __nv_bfloat16 hb = __float2bfloat16(v[c]);
        float r = v[c] - __bfloat162float(hb);
        __nv_bfloat16 lb = __float2bfloat16(r);
        hi[c] = __bfloat16_as_ushort(hb);
        lo[c] = __bfloat16_as_ushort(lb);
    }
    const size_t idx = (size_t)b * DD + t * 4;
    uint2 ph = make_uint2(((uint32_t)hi[1] << 16) | hi[0], ((uint32_t)hi[3] << 16) | hi[2]);
    uint2 pl = make_uint2(((uint32_t)lo[1] << 16) | lo[0], ((uint32_t)lo[3] << 16) | lo[2]);
    *(uint2*)(g_bow_hi + idx) = ph;
    *(uint2*)(g_bow_lo + idx) = pl;
}

// ---------------------------------------------------------------------------
// Convert W1 fp32 -> (hi, lo) bf16 pair (row-major [K][N]).
// ---------------------------------------------------------------------------
__global__ __launch_bounds__(256) void convert_w1(const float* __restrict__ W1)
{
    const int i = (blockIdx.x * 256 + threadIdx.x) * 4;
    const float4 v4 = *(const float4*)(W1 + i);
    const float v[4] = {v4.x, v4.y, v4.z, v4.w};
    unsigned short hi[4], lo[4];
#pragma unroll
    for (int c = 0; c < 4; c++) {
        __nv_bfloat16 hb = __float2bfloat16(v[c]);
        float r = v[c] - __bfloat162float(hb);
        __nv_bfloat16 lb = __float2bfloat16(r);
        hi[c] = __bfloat16_as_ushort(hb);
        lo[c] = __bfloat16_as_ushort(lb);
    }
    uint2 ph = make_uint2(((uint32_t)hi[1] << 16) | hi[0], ((uint32_t)hi[3] << 16) | hi[2]);
    uint2 pl = make_uint2(((uint32_t)lo[1] << 16) | lo[0], ((uint32_t)lo[3] << 16) | lo[2]);
    *(uint2*)(g_w1_hi + i) = ph;
    *(uint2*)(g_w1_lo + i) = pl;
}

// ---------------------------------------------------------------------------
// Convert W2 fp32 [768][100] -> zero-padded bf16 hi/lo [768][128].
// 24576 threads x 4 cols.
// ---------------------------------------------------------------------------
__global__ __launch_bounds__(256) void convert_w2(const float* __restrict__ W2)
{
    const int idx = blockIdx.x * 256 + threadIdx.x;   // 0..24575
    const int k = idx >> 5;
    const int c = (idx & 31) * 4;
    unsigned short hi[4], lo[4];
#pragma unroll
    for (int j = 0; j < 4; j++) {
        const int col = c + j;
        const float v = (col < CC) ? W2[(size_t)k * CC + col] : 0.f;
        __nv_bfloat16 hb = __float2bfloat16(v);
        float r = v - __bfloat162float(hb);
        __nv_bfloat16 lb = __float2bfloat16(r);
        hi[j] = __bfloat16_as_ushort(hb);
        lo[j] = __bfloat16_as_ushort(lb);
    }
    const size_t o = (size_t)k * NP + c;
    *(uint2*)(g_w2p_hi + o) = make_uint2(((uint32_t)hi[1] << 16) | hi[0],
                                         ((uint32_t)hi[3] << 16) | hi[2]);
    *(uint2*)(g_w2p_lo + o) = make_uint2(((uint32_t)lo[1] << 16) | lo[0],
                                         ((uint32_t)lo[3] << 16) | lo[2]);
}

// ---------------------------------------------------------------------------
// Tensor-core helpers (mma.sync path; tcgen05 unavailable on this toolchain)
// ---------------------------------------------------------------------------
__device__ __forceinline__ uint32_t smem_u32(const void* p)
{
    return (uint32_t)__cvta_generic_to_shared(p);
}
__device__ __forceinline__ void ldsm4(uint32_t* r, uint32_t a)
{
    asm volatile("ldmatrix.sync.aligned.m8n8.x4.shared.b16 {%0,%1,%2,%3},[%4];"
                 : "=r"(r[0]), "=r"(r[1]), "=r"(r[2]), "=r"(r[3]) : "r"(a));
}
__device__ __forceinline__ void ldsm4t(uint32_t* r, uint32_t a)
{
    asm volatile("ldmatrix.sync.aligned.m8n8.x4.trans.shared.b16 {%0,%1,%2,%3},[%4];"
                 : "=r"(r[0]), "=r"(r[1]), "=r"(r[2]), "=r"(r[3]) : "r"(a));
}
__device__ __forceinline__ void mma_bf16(float* d, const uint32_t* a, const uint32_t* b)
{
    asm volatile(
        "mma.sync.aligned.m16n8k16.row.col.f32.bf16.bf16.f32 "
        "{%0,%1,%2,%3}, {%4,%5,%6,%7}, {%8,%9}, {%0,%1,%2,%3};"
        : "+f"(d[0]), "+f"(d[1]), "+f"(d[2]), "+f"(d[3])
        : "r"(a[0]), "r"(a[1]), "r"(a[2]), "r"(a[3]), "r"(b[0]), "r"(b[1]));
}
__device__ __forceinline__ uint32_t pack_bf16x2_hi(float a, float b,
                                                   unsigned short* la, unsigned short* lb)
{
    __nv_bfloat16 ha = __float2bfloat16(a);
    __nv_bfloat16 hb = __float2bfloat16(b);
    *la = __bfloat16_as_ushort(__float2bfloat16(a - __bfloat162float(ha)));
    *lb = __bfloat16_as_ushort(__float2bfloat16(b - __bfloat162float(hb)));
    return (uint32_t)__bfloat16_as_ushort(ha) | ((uint32_t)__bfloat16_as_ushort(hb) << 16);
}

// ---------------------------------------------------------------------------
// gemm1: h = relu(bow @ W1 + b1), bf16-split x3, product-major MMA order.
// BM=128, BN=96, BK=16. grid (8, 16) = 128 CTAs (one wave).
// 8 warps as 4(m) x 2(n); warp tile 32x48; emits h as bf16 hi/lo.
// ---------------------------------------------------------------------------
#define AST 24     // A smem row stride (halves) = 48 B
#define BST 104    // B smem row stride (halves) = 208 B

__global__ __launch_bounds__(256) void gemm1_mma96(
    const float* __restrict__ bias)
{
    __shared__ __align__(16) __nv_bfloat16 sA[2][2][128 * AST];
    __shared__ __align__(16) __nv_bfloat16 sB[2][2][16 * BST];

    const int tid    = threadIdx.x;
    const int lane   = tid & 31;
    const int wid    = tid >> 5;
    const int warp_m = wid & 3;
    const int warp_n = wid >> 2;

    const int block_row = blockIdx.y * 128;
    const int block_col = blockIdx.x * 96;

    int a_p[2], a_r[2], a_c[2];
    const __nv_bfloat16* Aptr[2];
#pragma unroll
    for (int e = 0; e < 2; e++) {
        const int u = tid + e * 256;
        a_p[e] = u >> 8;
        a_r[e] = (u & 255) >> 1;
        a_c[e] = (u & 1) * 8;
        Aptr[e] = (a_p[e] ? g_bow_lo : g_bow_hi)
                  + (size_t)(block_row + a_r[e]) * DD + a_c[e];
    }
    int b_p[2], b_r[2], b_c[2], b_ok[2];
    const __nv_bfloat16* Bptr[2];
#pragma unroll
    for (int e = 0; e < 2; e++) {
        const int u = tid + e * 256;
        b_ok[e] = (u < 384);
        const int uu = b_ok[e] ? u : 0;
        b_p[e] = uu / 192;
        const int rem = uu - b_p[e] * 192;
        b_r[e] = rem / 12;
        b_c[e] = (rem - b_r[e] * 12) * 8;
        Bptr[e] = (b_p[e] ? g_w1_lo : g_w1_hi)
                  + (size_t)b_r[e] * DD + block_col + b_c[e];
    }

    float acc[2][6][4];
#pragma unroll
    for (int mt = 0; mt < 2; mt++)
#pragma unroll
        for (int nt = 0; nt < 6; nt++)
#pragma unroll
            for (int q = 0; q < 4; q++) acc[mt][nt][q] = 0.f;

#pragma unroll
    for (int e = 0; e < 2; e++) {
        *(uint4*)&sA[0][a_p[e]][a_r[e] * AST + a_c[e]] = *(const uint4*)(Aptr[e]);
        if (b_ok[e])
            *(uint4*)&sB[0][b_p[e]][b_r[e] * BST + b_c[e]] = *(const uint4*)(Bptr[e]);
    }
    __syncthreads();

    const int NT = DD / 16;
    int aoff[2];
#pragma unroll
    for (int mt = 0; mt < 2; mt++)
        aoff[mt] = (warp_m * 32 + mt * 16 + (lane & 15)) * AST + (lane >> 4) * 8;
    int boff[3];
#pragma unroll
    for (int g = 0; g < 3; g++)
        boff[g] = (lane & 15) * BST + warp_n * 48 + g * 16 + (lane >> 4) * 8;

    for (int kt = 0; kt < NT; kt++) {
        const int cur = kt & 1;
        const int nxt = cur ^ 1;
        const bool has_next = (kt + 1 < NT);

        uint4 pa[2], pb[2];
        if (has_next) {
            const int k0 = (kt + 1) * 16;
#pragma unroll
            for (int e = 0; e < 2; e++) {
                pa[e] = *(const uint4*)(Aptr[e] + k0);
                if (b_ok[e]) pb[e] = *(const uint4*)(Bptr[e] + (size_t)k0 * DD);
            }
        }

        uint32_t af[2][2][4];
#pragma unroll
        for (int p = 0; p < 2; p++)
#pragma unroll
            for (int mt = 0; mt < 2; mt++)
                ldsm4(af[p][mt], smem_u32(&sA[cur][p][aoff[mt]]));

        uint32_t bfr[2][6][2];
#pragma unroll
        for (int p = 0; p < 2; p++)
#pragma unroll
            for (int g = 0; g < 3; g++) {
                uint32_t r[4];
                ldsm4t(r, smem_u32(&sB[cur][p][boff[g]]));
                bfr[p][2 * g + 0][0] = r[0]; bfr[p][2 * g + 0][1] = r[1];
                bfr[p][2 * g + 1][0] = r[2]; bfr[p][2 * g + 1][1] = r[3];
            }

        // product-major: 12 independent MMAs back-to-back per product
#pragma unroll
        for (int mt = 0; mt < 2; mt++)
#pragma unroll
            for (int nt = 0; nt < 6; nt++)
                mma_bf16(acc[mt][nt], af[0][mt], bfr[0][nt]);  // hi*hi
#pragma unroll
        for (int mt = 0; mt < 2; mt++)
#pragma unroll
            for (int nt = 0; nt < 6; nt++)
                mma_bf16(acc[mt][nt], af[0][mt], bfr[1][nt]);  // hi*lo
#pragma unroll
        for (int mt = 0; mt < 2; mt++)
#pragma unroll
            for (int nt = 0; nt < 6; nt++)
                mma_bf16(acc[mt][nt], af[1][mt], bfr[0][nt]);  // lo*hi

        if (has_next) {
#pragma unroll
            for (int e = 0; e < 2; e++) {
                *(uint4*)&sA[nxt][a_p[e]][a_r[e] * AST + a_c[e]] = pa[e];
                if (b_ok[e])
                    *(uint4*)&sB[nxt][b_p[e]][b_r[e] * BST + b_c[e]] = pb[e];
            }
            __syncthreads();
        }
    }

    // epilogue: bias + relu, emit h as bf16 hi/lo planes
#pragma unroll
    for (int mt = 0; mt < 2; mt++) {
        const int row0 = block_row + warp_m * 32 + mt * 16 + (lane >> 2);
#pragma unroll
        for (int nt = 0; nt < 6; nt++) {
            const int col = block_col + warp_n * 48 + nt * 8 + (lane & 3) * 2;
            const float b0 = bias[col], b1v = bias[col + 1];
            const float v0x = fmaxf(acc[mt][nt][0] + b0, 0.f);
            const float v0y = fmaxf(acc[mt][nt][1] + b1v, 0.f);
            const float v1x = fmaxf(acc[mt][nt][2] + b0, 0.f);
            const float v1y = fmaxf(acc[mt][nt][3] + b1v, 0.f);
            unsigned short l0, l1, l2, l3;
            const uint32_t h0 = pack_bf16x2_hi(v0x, v0y, &l0, &l1);
            const uint32_t h1 = pack_bf16x2_hi(v1x, v1y, &l2, &l3);
            *(uint32_t*)(g_h_hi + (size_t)row0 * DD + col) = h0;
            *(uint32_t*)(g_h_lo + (size_t)row0 * DD + col) =
                (uint32_t)l0 | ((uint32_t)l1 << 16);
            *(uint32_t*)(g_h_hi + (size_t)(row0 + 8) * DD + col) = h1;
            *(uint32_t*)(g_h_lo + (size_t)(row0 + 8) * DD + col) =
                (uint32_t)l2 | ((uint32_t)l3 << 16);
        }
    }
}

// ---------------------------------------------------------------------------
// gemm2: partial[ksl] = h[64 rows, kslice=192] @ W2pad[., 128], bf16-split x3.
// BM=64, BN=128, BK=16. grid (G2K, 32) = 128 CTAs (one wave).
// 8 warps as 2(m) x 4(n); warp tile 32x32.
// ---------------------------------------------------------------------------
#define BST2 136   // B smem row stride (halves) = 272 B

__global__ __launch_bounds__(256) void gemm2_mma(void)
{
    __shared__ __align__(16) __nv_bfloat16 sA[2][2][64 * AST];
    __shared__ __align__(16) __nv_bfloat16 sB[2][2][16 * BST2];

    const int tid    = threadIdx.x;
    const int lane   = tid & 31;
    const int wid    = tid >> 5;
    const int warp_m = wid & 1;     // 0..1 -> 32 rows
    const int warp_n = wid >> 1;    // 0..3 -> 32 cols

    const int ksl       = blockIdx.x;
    const int block_row = blockIdx.y * 64;
    const int kbase     = ksl * (DD / G2K);   // 192

    // A fill: 64r x 16k x 2p = 256 uint4 -> 1/thread
    const int a_p = tid >> 7;
    const int a_r = (tid & 127) >> 1;
    const int a_c = (tid & 1) * 8;
    const __nv_bfloat16* Aptr = (a_p ? g_h_lo : g_h_hi)
                                + (size_t)(block_row + a_r) * DD + kbase + a_c;
    // B fill: 16k x 128c x 2p = 512 uint4 -> 2/thread
    int b_p[2], b_r[2], b_c[2];
    const __nv_bfloat16* Bptr[2];
#pragma unroll
    for (int e = 0; e < 2; e++) {
        const int u = tid + e * 256;
        b_p[e] = u >> 8;
        b_r[e] = (u & 255) >> 4;
        b_c[e] = (u & 15) * 8;
        Bptr[e] = (b_p[e] ? g_w2p_lo : g_w2p_hi)
                  + (size_t)(kbase + b_r[e]) * NP + b_c[e];
    }

    float acc[2][4][4];
#pragma unroll
    for (int mt = 0; mt < 2; mt++)
#pragma unroll
        for (int nt = 0; nt < 4; nt++)
#pragma unroll
            for (int q = 0; q < 4; q++) acc[mt][nt][q] = 0.f;

    *(uint4*)&sA[0][a_p][a_r * AST + a_c] = *(const uint4*)(Aptr);
#pragma unroll
    for (int e = 0; e < 2; e++)
        *(uint4*)&sB[0][b_p[e]][b_r[e] * BST2 + b_c[e]] = *(const uint4*)(Bptr[e]);
    __syncthreads();

    const int NT = (DD / G2K) / 16;   // 12
    int aoff[2];
#pragma unroll
    for (int mt = 0; mt < 2; mt++)
        aoff[mt] = (warp_m * 32 + mt * 16 + (lane & 15)) * AST + (lane >> 4) * 8;
    int boff[2];
#pragma unroll
    for (int g = 0; g < 2; g++)
        boff[g] = (lane & 15) * BST2 + warp_n * 32 + g * 16 + (lane >> 4) * 8;

    for (int kt = 0; kt < NT; kt++) {
        const int cur = kt & 1;
        const int nxt = cur ^ 1;
        const bool has_next = (kt + 1 < NT);

        uint4 pa, pb[2];
        if (has_next) {
            const int k0 = (kt + 1) * 16;
            pa = *(const uint4*)(Aptr + k0);
#pragma unroll
            for (int e = 0; e < 2; e++)
                pb[e] = *(const uint4*)(Bptr[e] + (size_t)k0 * NP);
        }

        uint32_t af[2][2][4];
#pragma unroll
        for (int p = 0; p < 2; p++)
#pragma unroll
            for (int mt = 0; mt < 2; mt++)
                ldsm4(af[p][mt], smem_u32(&sA[cur][p][aoff[mt]]));

        uint32_t bfr[2][4][2];
#pragma unroll
        for (int p = 0; p < 2; p++)
#pragma unroll
            for (int g = 0; g < 2; g++) {
                uint32_t r[4];
                ldsm4t(r, smem_u32(&sB[cur][p][boff[g]]));
                bfr[p][2 * g + 0][0] = r[0]; bfr[p][2 * g + 0][1] = r[1];
                bfr[p][2 * g + 1][0] = r[2]; bfr[p][2 * g + 1][1] = r[3];
            }

#pragma unroll
        for (int mt = 0; mt < 2; mt++)
#pragma unroll
            for (int nt = 0; nt < 4; nt++)
                mma_bf16(acc[mt][nt], af[0][mt], bfr[0][nt]);
#pragma unroll
        for (int mt = 0; mt < 2; mt++)
#pragma unroll
            for (int nt = 0; nt < 4; nt++)
                mma_bf16(acc[mt][nt], af[0][mt], bfr[1][nt]);
#pragma unroll
        for (int mt = 0; mt < 2; mt++)
#pragma unroll
            for (int nt = 0; nt < 4; nt++)
                mma_bf16(acc[mt][nt], af[1][mt], bfr[0][nt]);

        if (has_next) {
            *(uint4*)&sA[nxt][a_p][a_r * AST + a_c] = pa;
#pragma unroll
            for (int e = 0; e < 2; e++)
                *(uint4*)&sB[nxt][b_p[e]][b_r[e] * BST2 + b_c[e]] = pb[e];
            __syncthreads();
        }
    }

    // store fp32 partials
#pragma unroll
    for (int mt = 0; mt < 2; mt++) {
        const int row0 = block_row + warp_m * 32 + mt * 16 + (lane >> 2);
#pragma unroll
        for (int nt = 0; nt < 4; nt++) {
            const int col = warp_n * 32 + nt * 8 + (lane & 3) * 2;
            *(float2*)(&g_p2[ksl][row0][col]) =
                make_float2(acc[mt][nt][0], acc[mt][nt][1]);
            *(float2*)(&g_p2[ksl][row0 + 8][col]) =
                make_float2(acc[mt][nt][2], acc[mt][nt][3]);
        }
    }
}

// ---------------------------------------------------------------------------
// Reduce gemm2 partials + bias, write both output copies.
// ---------------------------------------------------------------------------
__global__ __launch_bounds__(256) void reduce_kernel(
    const float* __restrict__ bias,
    float* __restrict__ out,
    float* __restrict__ out2)
{
    const int idx = blockIdx.x * 256 + threadIdx.x;
    if (idx >= BB * CC) return;
    const int b = idx / CC;
    const int c = idx - b * CC;
    float v = bias[c];
#pragma unroll
    for (int s = 0; s < G2K; s++) v += g_p2[s][b][c];
    out[idx] = v;
    if (out2) out2[idx] = v;
}

// ---------------------------------------------------------------------------
extern "C" void kernel_launch(void* const* d_in, const int* in_sizes, int n_in,
                              void* d_out, int out_size)
{
    const int*   input_ids = (const int*)d_in[0];
    const int*   attn_mask = (const int*)d_in[1];
    const float* emb       = (const float*)d_in[2];
    const float* W1        = (const float*)d_in[3];
    const float* b1        = (const float*)d_in[4];
    const float* W2        = (const float*)d_in[5];
    const float* b2        = (const float*)d_in[6];
    float*       out       = (float*)d_out;

    // Weight conversions (independent of pooling; launched first)
    convert_w1<<<(DD * DD) / (256 * 4), 256>>>(W1);
    convert_w2<<<(DD * 32) / 256, 256>>>(W2);

    // Stage 1: pooling
    {
        dim3 grid(BB, PSL);
        pool_partial<<<grid, 192>>>(input_ids, attn_mask, emb);
        pool_combine_split<<<BB, 192>>>();
    }

    // Stage 2: h = relu(bow @ W1 + b1) -> bf16 hi/lo
    {
        dim3 grid(DD / 96, BB / 128);    // (8, 16) = 128 CTAs
        gemm1_mma96<<<grid, 256>>>(b1);
    }

    // Stage 3: scores = h @ W2 + b2 (tensor-core split-K + reduce)
    {
        dim3 grid(G2K, BB / 64);         // (4, 32) = 128 CTAs
        gemm2_mma<<<grid, 256>>>();
        float* out2 = (out_size >= 2 * BB * CC) ? (out + (size_t)BB * CC) : nullptr;
        reduce_kernel<<<(BB * CC + 255) / 256, 256>>>(b2, out, out2);
    }
}

// round 13
// speedup vs baseline: 1.2298x; 1.1114x over previous
#include <cuda_runtime.h>
#include <cuda_bf16.h>
#include <cuda_fp16.h>
#include <cstdint>

#define BB 2048
#define SS 256
#define DD 768
#define CC 100
#define NP 128         // padded N for gemm2
#define PSL 2          // pooling sequence slices (128 tokens each)
#define G2K 4          // gemm2 K slices (192 each)

// Scratch (no cudaMalloc allowed)
__device__ __half g_emb16[(size_t)30522 * DD];
__device__ float g_part[PSL][BB][DD];
__device__ float g_cntf[PSL][BB];
__device__ float g_p2[G2K][BB][NP];
__device__ __nv_bfloat16 g_bow_hi[(size_t)BB * DD];
__device__ __nv_bfloat16 g_bow_lo[(size_t)BB * DD];
__device__ __nv_bfloat16 g_w1_hi[(size_t)DD * DD];    // W1 row-major [K][N]
__device__ __nv_bfloat16 g_w1_lo[(size_t)DD * DD];
__device__ __nv_bfloat16 g_w2p_hi[(size_t)DD * NP];   // W2 padded [K][128]
__device__ __nv_bfloat16 g_w2p_lo[(size_t)DD * NP];
__device__ __nv_bfloat16 g_h_hi[(size_t)BB * DD];
__device__ __nv_bfloat16 g_h_lo[(size_t)BB * DD];

// ---------------------------------------------------------------------------
// Convert embedding table fp32 -> fp16 (halves pool gather bytes).
// ---------------------------------------------------------------------------
__global__ __launch_bounds__(256) void convert_emb(const float* __restrict__ emb)
{
    const size_t idx = ((size_t)blockIdx.x * 256 + threadIdx.x) * 8;
    if (idx >= (size_t)30522 * DD) return;
    const float4 a = *(const float4*)(emb + idx);
    const float4 b = *(const float4*)(emb + idx + 4);
    __half2 h0 = __floats2half2_rn(a.x, a.y);
    __half2 h1 = __floats2half2_rn(a.z, a.w);
    __half2 h2 = __floats2half2_rn(b.x, b.y);
    __half2 h3 = __floats2half2_rn(b.z, b.w);
    uint4 o;
    o.x = *(uint32_t*)&h0; o.y = *(uint32_t*)&h1;
    o.z = *(uint32_t*)&h2; o.w = *(uint32_t*)&h3;
    *(uint4*)(g_emb16 + idx) = o;
}

// ---------------------------------------------------------------------------
// Stage 1a: partial pooling over fp16 table. grid (BB, PSL); 128 tokens/block.
// 192 threads; each owns 4 halves (uint2) of the 768-dim row.
// ---------------------------------------------------------------------------
__global__ __launch_bounds__(192) void pool_partial(
    const int* __restrict__ ids,
    const int* __restrict__ mask)
{
    const int b  = blockIdx.x;
    const int sl = blockIdx.y;
    const int t  = threadIdx.x;

    __shared__ int s_ids[128];
    __shared__ int s_cnt;
    if (t == 0) s_cnt = 0;
    __syncthreads();

    if (t < 128) {
        const int off = b * SS + sl * 128 + t;
        if (mask[off] != 0) {
            const int pos = atomicAdd(&s_cnt, 1);
            s_ids[pos] = ids[off];
        }
    }
    __syncthreads();
    const int cnt = s_cnt;

    float a0 = 0.f, a1 = 0.f, a2 = 0.f, a3 = 0.f;
    const int col = t * 4;
    int s = 0;
    for (; s + 4 <= cnt; s += 4) {
        const uint2 u0 = *(const uint2*)(g_emb16 + (size_t)s_ids[s + 0] * DD + col);
        const uint2 u1 = *(const uint2*)(g_emb16 + (size_t)s_ids[s + 1] * DD + col);
        const uint2 u2 = *(const uint2*)(g_emb16 + (size_t)s_ids[s + 2] * DD + col);
        const uint2 u3 = *(const uint2*)(g_emb16 + (size_t)s_ids[s + 3] * DD + col);
        const float2 p0 = __half22float2(*(const __half2*)&u0.x);
        const float2 q0 = __half22float2(*(const __half2*)&u0.y);
        const float2 p1 = __half22float2(*(const __half2*)&u1.x);
        const float2 q1 = __half22float2(*(const __half2*)&u1.y);
        const float2 p2 = __half22float2(*(const __half2*)&u2.x);
        const float2 q2 = __half22float2(*(const __half2*)&u2.y);
        const float2 p3 = __half22float2(*(const __half2*)&u3.x);
        const float2 q3 = __half22float2(*(const __half2*)&u3.y);
        a0 += (p0.x + p1.x) + (p2.x + p3.x);
        a1 += (p0.y + p1.y) + (p2.y + p3.y);
        a2 += (q0.x + q1.x) + (q2.x + q3.x);
        a3 += (q0.y + q1.y) + (q2.y + q3.y);
    }
    for (; s < cnt; s++) {
        const uint2 u = *(const uint2*)(g_emb16 + (size_t)s_ids[s] * DD + col);
        const float2 p = __half22float2(*(const __half2*)&u.x);
        const float2 q = __half22float2(*(const __half2*)&u.y);
        a0 += p.x; a1 += p.y; a2 += q.x; a3 += q.y;
    }
    *(float4*)(&g_part[sl][b][col]) = make_float4(a0, a1, a2, a3);
    if (t == 0) g_cntf[sl][b] = (float)cnt;
}

// ---------------------------------------------------------------------------
// Stage 1b: combine slices, emit bow as bf16 (hi, lo) split.
// ---------------------------------------------------------------------------
__global__ __launch_bounds__(192) void pool_combine_split(void)
{
    const int b = blockIdx.x;
    const int t = threadIdx.x;
    const float inv = 1.0f / (g_cntf[0][b] + g_cntf[1][b]);
    float v[4] = {0.f, 0.f, 0.f, 0.f};
#pragma unroll
    for (int sl = 0; sl < PSL; sl++) {
        const float4 p = *((const float4*)(&g_part[sl][b][0]) + t);
        v[0] += p.x; v[1] += p.y; v[2] += p.z; v[3] += p.w;
    }
#pragma unroll
    for (int c = 0; c < 4; c++) v[c] *= inv;

    unsigned short hi[4], lo[4];
#pragma unroll
    for (int c = 0; c < 4; c++) {
        __nv_bfloat16 hb = __float2bfloat16(v[c]);
        float r = v[c] - __bfloat162float(hb);
        __nv_bfloat16 lb = __float2bfloat16(r);
        hi[c] = __bfloat16_as_ushort(hb);
        lo[c] = __bfloat16_as_ushort(lb);
    }
    const size_t idx = (size_t)b * DD + t * 4;
    uint2 ph = make_uint2(((uint32_t)hi[1] << 16) | hi[0], ((uint32_t)hi[3] << 16) | hi[2]);
    uint2 pl = make_uint2(((uint32_t)lo[1] << 16) | lo[0], ((uint32_t)lo[3] << 16) | lo[2]);
    *(uint2*)(g_bow_hi + idx) = ph;
    *(uint2*)(g_bow_lo + idx) = pl;
}

// ---------------------------------------------------------------------------
// Convert W1 fp32 -> (hi, lo) bf16 pair (row-major [K][N]).
// ---------------------------------------------------------------------------
__global__ __launch_bounds__(256) void convert_w1(const float* __restrict__ W1)
{
    const int i = (blockIdx.x * 256 + threadIdx.x) * 4;
    const float4 v4 = *(const float4*)(W1 + i);
    const float v[4] = {v4.x, v4.y, v4.z, v4.w};
    unsigned short hi[4], lo[4];
#pragma unroll
    for (int c = 0; c < 4; c++) {
        __nv_bfloat16 hb = __float2bfloat16(v[c]);
        float r = v[c] - __bfloat162float(hb);
        __nv_bfloat16 lb = __float2bfloat16(r);
        hi[c] = __bfloat16_as_ushort(hb);
        lo[c] = __bfloat16_as_ushort(lb);
    }
    uint2 ph = make_uint2(((uint32_t)hi[1] << 16) | hi[0], ((uint32_t)hi[3] << 16) | hi[2]);
    uint2 pl = make_uint2(((uint32_t)lo[1] << 16) | lo[0], ((uint32_t)lo[3] << 16) | lo[2]);
    *(uint2*)(g_w1_hi + i) = ph;
    *(uint2*)(g_w1_lo + i) = pl;
}

// ---------------------------------------------------------------------------
// Convert W2 fp32 [768][100] -> zero-padded bf16 hi/lo [768][128].
// ---------------------------------------------------------------------------
__global__ __launch_bounds__(256) void convert_w2(const float* __restrict__ W2)
{
    const int idx = blockIdx.x * 256 + threadIdx.x;
    const int k = idx >> 5;
    const int c = (idx & 31) * 4;
    unsigned short hi[4], lo[4];
#pragma unroll
    for (int j = 0; j < 4; j++) {
        const int col = c + j;
        const float v = (col < CC) ? W2[(size_t)k * CC + col] : 0.f;
        __nv_bfloat16 hb = __float2bfloat16(v);
        float r = v - __bfloat162float(hb);
        __nv_bfloat16 lb = __float2bfloat16(r);
        hi[j] = __bfloat16_as_ushort(hb);
        lo[j] = __bfloat16_as_ushort(lb);
    }
    const size_t o = (size_t)k * NP + c;
    *(uint2*)(g_w2p_hi + o) = make_uint2(((uint32_t)hi[1] << 16) | hi[0],
                                         ((uint32_t)hi[3] << 16) | hi[2]);
    *(uint2*)(g_w2p_lo + o) = make_uint2(((uint32_t)lo[1] << 16) | lo[0],
                                         ((uint32_t)lo[3] << 16) | lo[2]);
}

// ---------------------------------------------------------------------------
// Tensor-core helpers
// ---------------------------------------------------------------------------
__device__ __forceinline__ uint32_t smem_u32(const void* p)
{
    return (uint32_t)__cvta_generic_to_shared(p);
}
__device__ __forceinline__ void ldsm4(uint32_t* r, uint32_t a)
{
    asm volatile("ldmatrix.sync.aligned.m8n8.x4.shared.b16 {%0,%1,%2,%3},[%4];"
                 : "=r"(r[0]), "=r"(r[1]), "=r"(r[2]), "=r"(r[3]) : "r"(a));
}
__device__ __forceinline__ void ldsm4t(uint32_t* r, uint32_t a)
{
    asm volatile("ldmatrix.sync.aligned.m8n8.x4.trans.shared.b16 {%0,%1,%2,%3},[%4];"
                 : "=r"(r[0]), "=r"(r[1]), "=r"(r[2]), "=r"(r[3]) : "r"(a));
}
__device__ __forceinline__ void mma_bf16(float* d, const uint32_t* a, const uint32_t* b)
{
    asm volatile(
        "mma.sync.aligned.m16n8k16.row.col.f32.bf16.bf16.f32 "
        "{%0,%1,%2,%3}, {%4,%5,%6,%7}, {%8,%9}, {%0,%1,%2,%3};"
        : "+f"(d[0]), "+f"(d[1]), "+f"(d[2]), "+f"(d[3])
        : "r"(a[0]), "r"(a[1]), "r"(a[2]), "r"(a[3]), "r"(b[0]), "r"(b[1]));
}
__device__ __forceinline__ uint32_t pack_bf16x2_hi(float a, float b,
                                                   unsigned short* la, unsigned short* lb)
{
    __nv_bfloat16 ha = __float2bfloat16(a);
    __nv_bfloat16 hb = __float2bfloat16(b);
    *la = __bfloat16_as_ushort(__float2bfloat16(a - __bfloat162float(ha)));
    *lb = __bfloat16_as_ushort(__float2bfloat16(b - __bfloat162float(hb)));
    return (uint32_t)__bfloat16_as_ushort(ha) | ((uint32_t)__bfloat16_as_ushort(hb) << 16);
}

// ---------------------------------------------------------------------------
// gemm1: h = relu(bow @ W1 + b1), bf16-split x3, BK=32 (24 iters, half the
// barriers of BK=16). BM=128, BN=96. grid (8, 16) = 128 CTAs (one wave).
// 8 warps 4(m) x 2(n); warp tile 32x48. Dynamic smem 66 KB.
// ---------------------------------------------------------------------------
#define AST32 40   // A smem row stride (halves) = 80 B, 16B mult, conflict-free
#define BST 104    // B smem row stride (halves) = 208 B, 16B mult, conflict-free
#define SA_HALVES (2 * 2 * 128 * AST32)   // 20480
#define SB_HALVES (2 * 2 * 32 * BST)      // 13312
#define G1_SMEM ((SA_HALVES + SB_HALVES) * 2)   // 67584 bytes

__global__ __launch_bounds__(256) void gemm1_mma96(
    const float* __restrict__ bias)
{
    extern __shared__ __align__(16) __nv_bfloat16 smem[];
    __nv_bfloat16* sA = smem;                  // [st][p][128*AST32]
    __nv_bfloat16* sB = smem + SA_HALVES;      // [st][p][32*BST]

    const int tid    = threadIdx.x;
    const int lane   = tid & 31;
    const int wid    = tid >> 5;
    const int warp_m = wid & 3;
    const int warp_n = wid >> 2;

    const int block_row = blockIdx.y * 128;
    const int block_col = blockIdx.x * 96;

    // A fill: 128r x 32k x 2p = 1024 uint4 -> 4/thread
    int a_idx[4];
    const __nv_bfloat16* Aptr[4];
#pragma unroll
    for (int e = 0; e < 4; e++) {
        const int u = tid + e * 256;
        const int p = u >> 9;
        const int r = (u & 511) >> 2;
        const int c = (u & 3) * 8;
        a_idx[e] = p * (128 * AST32) + r * AST32 + c;
        Aptr[e] = (p ? g_bow_lo : g_bow_hi) + (size_t)(block_row + r) * DD + c;
    }
    // B fill: 32k x 96c x 2p = 768 uint4 -> 3/thread
    int b_idx[3];
    const __nv_bfloat16* Bptr[3];
#pragma unroll
    for (int e = 0; e < 3; e++) {
        const int u = tid + e * 256;
        const int p = u / 384;
        const int rem = u - p * 384;
        const int r = rem / 12;
        const int c = (rem - r * 12) * 8;
        b_idx[e] = p * (32 * BST) + r * BST + c;
        Bptr[e] = (p ? g_w1_lo : g_w1_hi) + (size_t)r * DD + block_col + c;
    }

    float acc[2][6][4];
#pragma unroll
    for (int mt = 0; mt < 2; mt++)
#pragma unroll
        for (int nt = 0; nt < 6; nt++)
#pragma unroll
            for (int q = 0; q < 4; q++) acc[mt][nt][q] = 0.f;

    // preload k-tile 0 into stage 0
#pragma unroll
    for (int e = 0; e < 4; e++)
        *(uint4*)&sA[a_idx[e]] = *(const uint4*)(Aptr[e]);
#pragma unroll
    for (int e = 0; e < 3; e++)
        *(uint4*)&sB[b_idx[e]] = *(const uint4*)(Bptr[e]);
    __syncthreads();

    const int NT = DD / 32;   // 24
    for (int kt = 0; kt < NT; kt++) {
        const int cur = kt & 1;
        const int nxt = cur ^ 1;
        const bool has_next = (kt + 1 < NT);
        const int curA = cur * (2 * 128 * AST32);
        const int curB = cur * (2 * 32 * BST);

        uint4 pa[4], pb[3];
        if (has_next) {
            const int k0 = (kt + 1) * 32;
#pragma unroll
            for (int e = 0; e < 4; e++)
                pa[e] = *(const uint4*)(Aptr[e] + k0);
#pragma unroll
            for (int e = 0; e < 3; e++)
                pb[e] = *(const uint4*)(Bptr[e] + (size_t)k0 * DD);
        }

#pragma unroll
        for (int ks = 0; ks < 2; ks++) {
            uint32_t af[2][2][4];
#pragma unroll
            for (int p = 0; p < 2; p++)
#pragma unroll
                for (int mt = 0; mt < 2; mt++) {
                    const int off = curA + p * (128 * AST32)
                        + (warp_m * 32 + mt * 16 + (lane & 15)) * AST32
                        + ks * 16 + (lane >> 4) * 8;
                    ldsm4(af[p][mt], smem_u32(&sA[off]));
                }
            uint32_t bfr[2][6][2];
#pragma unroll
            for (int p = 0; p < 2; p++)
#pragma unroll
                for (int g = 0; g < 3; g++) {
                    const int off = curB + p * (32 * BST)
                        + (ks * 16 + (lane & 15)) * BST
                        + warp_n * 48 + g * 16 + (lane >> 4) * 8;
                    uint32_t r[4];
                    ldsm4t(r, smem_u32(&sB[off]));
                    bfr[p][2 * g + 0][0] = r[0]; bfr[p][2 * g + 0][1] = r[1];
                    bfr[p][2 * g + 1][0] = r[2]; bfr[p][2 * g + 1][1] = r[3];
                }
#pragma unroll
            for (int mt = 0; mt < 2; mt++)
#pragma unroll
                for (int nt = 0; nt < 6; nt++)
                    mma_bf16(acc[mt][nt], af[0][mt], bfr[0][nt]);
#pragma unroll
            for (int mt = 0; mt < 2; mt++)
#pragma unroll
                for (int nt = 0; nt < 6; nt++)
                    mma_bf16(acc[mt][nt], af[0][mt], bfr[1][nt]);
#pragma unroll
            for (int mt = 0; mt < 2; mt++)
#pragma unroll
                for (int nt = 0; nt < 6; nt++)
                    mma_bf16(acc[mt][nt], af[1][mt], bfr[0][nt]);
        }

        if (has_next) {
            const int nxtA = nxt * (2 * 128 * AST32);
            const int nxtB = nxt * (2 * 32 * BST);
#pragma unroll
            for (int e = 0; e < 4; e++)
                *(uint4*)&sA[nxtA + a_idx[e]] = pa[e];
#pragma unroll
            for (int e = 0; e < 3; e++)
                *(uint4*)&sB[nxtB + b_idx[e]] = pb[e];
            __syncthreads();
        }
    }

    // epilogue: bias + relu, emit h as bf16 hi/lo planes
#pragma unroll
    for (int mt = 0; mt < 2; mt++) {
        const int row0 = block_row + warp_m * 32 + mt * 16 + (lane >> 2);
#pragma unroll
        for (int nt = 0; nt < 6; nt++) {
            const int col = block_col + warp_n * 48 + nt * 8 + (lane & 3) * 2;
            const float b0 = bias[col], b1v = bias[col + 1];
            const float v0x = fmaxf(acc[mt][nt][0] + b0, 0.f);
            const float v0y = fmaxf(acc[mt][nt][1] + b1v, 0.f);
            const float v1x = fmaxf(acc[mt][nt][2] + b0, 0.f);
            const float v1y = fmaxf(acc[mt][nt][3] + b1v, 0.f);
            unsigned short l0, l1, l2, l3;
            const uint32_t h0 = pack_bf16x2_hi(v0x, v0y, &l0, &l1);
            const uint32_t h1 = pack_bf16x2_hi(v1x, v1y, &l2, &l3);
            *(uint32_t*)(g_h_hi + (size_t)row0 * DD + col) = h0;
            *(uint32_t*)(g_h_lo + (size_t)row0 * DD + col) =
                (uint32_t)l0 | ((uint32_t)l1 << 16);
            *(uint32_t*)(g_h_hi + (size_t)(row0 + 8) * DD + col) = h1;
            *(uint32_t*)(g_h_lo + (size_t)(row0 + 8) * DD + col) =
                (uint32_t)l2 | ((uint32_t)l3 << 16);
        }
    }
}

// ---------------------------------------------------------------------------
// gemm2: partial[ksl] = h[64 rows, kslice=192] @ W2pad[., 128], bf16-split x3.
// BM=64, BN=128, BK=16. grid (G2K, 32) = 128 CTAs.
// ---------------------------------------------------------------------------
#define AST 24
#define BST2 136

__global__ __launch_bounds__(256) void gemm2_mma(void)
{
    __shared__ __align__(16) __nv_bfloat16 sA[2][2][64 * AST];
    __shared__ __align__(16) __nv_bfloat16 sB[2][2][16 * BST2];

    const int tid    = threadIdx.x;
    const int lane   = tid & 31;
    const int wid    = tid >> 5;
    const int warp_m = wid & 1;
    const int warp_n = wid >> 1;

    const int ksl       = blockIdx.x;
    const int block_row = blockIdx.y * 64;
    const int kbase     = ksl * (DD / G2K);

    const int a_p = tid >> 7;
    const int a_r = (tid & 127) >> 1;
    const int a_c = (tid & 1) * 8;
    const __nv_bfloat16* Aptr = (a_p ? g_h_lo : g_h_hi)
                                + (size_t)(block_row + a_r) * DD + kbase + a_c;
    int b_p[2], b_r[2], b_c[2];
    const __nv_bfloat16* Bptr[2];
#pragma unroll
    for (int e = 0; e < 2; e++) {
        const int u = tid + e * 256;
        b_p[e] = u >> 8;
        b_r[e] = (u & 255) >> 4;
        b_c[e] = (u & 15) * 8;
        Bptr[e] = (b_p[e] ? g_w2p_lo : g_w2p_hi)
                  + (size_t)(kbase + b_r[e]) * NP + b_c[e];
    }

    float acc[2][4][4];
#pragma unroll
    for (int mt = 0; mt < 2; mt++)
#pragma unroll
        for (int nt = 0; nt < 4; nt++)
#pragma unroll
            for (int q = 0; q < 4; q++) acc[mt][nt][q] = 0.f;

    *(uint4*)&sA[0][a_p][a_r * AST + a_c] = *(const uint4*)(Aptr);
#pragma unroll
    for (int e = 0; e < 2; e++)
        *(uint4*)&sB[0][b_p[e]][b_r[e] * BST2 + b_c[e]] = *(const uint4*)(Bptr[e]);
    __syncthreads();

    const int NT = (DD / G2K) / 16;
    int aoff[2];
#pragma unroll
    for (int mt = 0; mt < 2; mt++)
        aoff[mt] = (warp_m * 32 + mt * 16 + (lane & 15)) * AST + (lane >> 4) * 8;
    int boff[2];
#pragma unroll
    for (int g = 0; g < 2; g++)
        boff[g] = (lane & 15) * BST2 + warp_n * 32 + g * 16 + (lane >> 4) * 8;

    for (int kt = 0; kt < NT; kt++) {
        const int cur = kt & 1;
        const int nxt = cur ^ 1;
        const bool has_next = (kt + 1 < NT);

        uint4 pa, pb[2];
        if (has_next) {
            const int k0 = (kt + 1) * 16;
            pa = *(const uint4*)(Aptr + k0);
#pragma unroll
            for (int e = 0; e < 2; e++)
                pb[e] = *(const uint4*)(Bptr[e] + (size_t)k0 * NP);
        }

        uint32_t af[2][2][4];
#pragma unroll
        for (int p = 0; p < 2; p++)
#pragma unroll
            for (int mt = 0; mt < 2; mt++)
                ldsm4(af[p][mt], smem_u32(&sA[cur][p][aoff[mt]]));

        uint32_t bfr[2][4][2];
#pragma unroll
        for (int p = 0; p < 2; p++)
#pragma unroll
            for (int g = 0; g < 2; g++) {
                uint32_t r[4];
                ldsm4t(r, smem_u32(&sB[cur][p][boff[g]]));
                bfr[p][2 * g + 0][0] = r[0]; bfr[p][2 * g + 0][1] = r[1];
                bfr[p][2 * g + 1][0] = r[2]; bfr[p][2 * g + 1][1] = r[3];
            }

#pragma unroll
        for (int mt = 0; mt < 2; mt++)
#pragma unroll
            for (int nt = 0; nt < 4; nt++)
                mma_bf16(acc[mt][nt], af[0][mt], bfr[0][nt]);
#pragma unroll
        for (int mt = 0; mt < 2; mt++)
#pragma unroll
            for (int nt = 0; nt < 4; nt++)
                mma_bf16(acc[mt][nt], af[0][mt], bfr[1][nt]);
#pragma unroll
        for (int mt = 0; mt < 2; mt++)
#pragma unroll
            for (int nt = 0; nt < 4; nt++)
                mma_bf16(acc[mt][nt], af[1][mt], bfr[0][nt]);

        if (has_next) {
            *(uint4*)&sA[nxt][a_p][a_r * AST + a_c] = pa;
#pragma unroll
            for (int e = 0; e < 2; e++)
                *(uint4*)&sB[nxt][b_p[e]][b_r[e] * BST2 + b_c[e]] = pb[e];
            __syncthreads();
        }
    }

#pragma unroll
    for (int mt = 0; mt < 2; mt++) {
        const int row0 = block_row + warp_m * 32 + mt * 16 + (lane >> 2);
#pragma unroll
        for (int nt = 0; nt < 4; nt++) {
            const int col = warp_n * 32 + nt * 8 + (lane & 3) * 2;
            *(float2*)(&g_p2[ksl][row0][col]) =
                make_float2(acc[mt][nt][0], acc[mt][nt][1]);
            *(float2*)(&g_p2[ksl][row0 + 8][col]) =
                make_float2(acc[mt][nt][2], acc[mt][nt][3]);
        }
    }
}

// ---------------------------------------------------------------------------
// Reduce gemm2 partials + bias, write both output copies.
// ---------------------------------------------------------------------------
__global__ __launch_bounds__(256) void reduce_kernel(
    const float* __restrict__ bias,
    float* __restrict__ out,
    float* __restrict__ out2)
{
    const int idx = blockIdx.x * 256 + threadIdx.x;
    if (idx >= BB * CC) return;
    const int b = idx / CC;
    const int c = idx - b * CC;
    float v = bias[c];
#pragma unroll
    for (int s = 0; s < G2K; s++) v += g_p2[s][b][c];
    out[idx] = v;
    if (out2) out2[idx] = v;
}

// ---------------------------------------------------------------------------
extern "C" void kernel_launch(void* const* d_in, const int* in_sizes, int n_in,
                              void* d_out, int out_size)
{
    const int*   input_ids = (const int*)d_in[0];
    const int*   attn_mask = (const int*)d_in[1];
    const float* emb       = (const float*)d_in[2];
    const float* W1        = (const float*)d_in[3];
    const float* b1        = (const float*)d_in[4];
    const float* W2        = (const float*)d_in[5];
    const float* b2        = (const float*)d_in[6];
    float*       out       = (float*)d_out;

    cudaFuncSetAttribute(gemm1_mma96, cudaFuncAttributeMaxDynamicSharedMemorySize, G1_SMEM);

    // Conversions
    {
        const size_t n_emb = (size_t)30522 * DD;
        convert_emb<<<(unsigned)((n_emb / 8 + 255) / 256), 256>>>(emb);
        convert_w1<<<(DD * DD) / (256 * 4), 256>>>(W1);
        convert_w2<<<(DD * 32) / 256, 256>>>(W2);
    }

    // Stage 1: pooling (fp16 gather)
    {
        dim3 grid(BB, PSL);
        pool_partial<<<grid, 192>>>(input_ids, attn_mask);
        pool_combine_split<<<BB, 192>>>();
    }

    // Stage 2: h = relu(bow @ W1 + b1) -> bf16 hi/lo (BK=32)
    {
        dim3 grid(DD / 96, BB / 128);    // (8, 16) = 128 CTAs
        gemm1_mma96<<<grid, 256, G1_SMEM>>>(b1);
    }

    // Stage 3: scores = h @ W2 + b2 (tensor-core split-K + reduce)
    {
        dim3 grid(G2K, BB / 64);         // (4, 32) = 128 CTAs
        gemm2_mma<<<grid, 256>>>();
        float* out2 = (out_size >= 2 * BB * CC) ? (out + (size_t)BB * CC) : nullptr;
        reduce_kernel<<<(BB * CC + 255) / 256, 256>>>(b2, out, out2);
    }
}